// round 1
// baseline (speedup 1.0000x reference)
#include <cuda_runtime.h>
#include <math.h>

#define Bz 32
#define NS 4096
#define Dm 256
#define Hh 4
#define DH 64
#define Ll 6
#define NQ 512
#define NK 1024
#define ATT_SCALE 0.125f

// ---------------- scratch (device globals; no allocation allowed) ----------------
__device__ float g_upd[(size_t)Bz * NS * Dm];   // running update_tensor state
__device__ float g_qn [(size_t)Bz * NQ * Dm];
__device__ float g_kn [(size_t)Bz * NK * Dm];
__device__ float g_Q  [(size_t)Bz * NQ * Dm];
__device__ float g_K  [(size_t)Bz * NK * Dm];
__device__ float g_V  [(size_t)Bz * NK * Dm];
__device__ float g_ctx[(size_t)Bz * NQ * Dm];
__device__ float g_h  [(size_t)Bz * NQ * Dm];
__device__ float g_t  [(size_t)Bz * NQ * Dm];
__device__ float g_r  [(size_t)Bz * NQ * Dm];

// ---------------- helpers ----------------
__device__ __forceinline__ float2 block_meanrstd(float x, float* red) {
    // 256 threads, D=256 elements, one per thread. Returns (mean, rstd).
    float s1 = x, s2 = x * x;
    #pragma unroll
    for (int o = 16; o > 0; o >>= 1) {
        s1 += __shfl_xor_sync(0xffffffffu, s1, o);
        s2 += __shfl_xor_sync(0xffffffffu, s2, o);
    }
    int w = threadIdx.x >> 5, ln = threadIdx.x & 31;
    if (ln == 0) { red[w] = s1; red[8 + w] = s2; }
    __syncthreads();
    float m = 0.f, q = 0.f;
    #pragma unroll
    for (int i = 0; i < 8; i++) { m += red[i]; q += red[8 + i]; }
    __syncthreads();  // allow red reuse
    m *= (1.0f / Dm);
    q = q * (1.0f / Dm) - m * m;
    return make_float2(m, rsqrtf(fmaxf(q, 0.f) + 1e-5f));
}

__device__ __forceinline__ float gelu_tanh(float x) {
    const float c = 0.7978845608028654f;  // sqrt(2/pi)
    float t = tanhf(c * (x + 0.044715f * x * x * x));
    return 0.5f * x * (1.0f + t);
}

// ---------------- kernels ----------------

// out[b, r, :] = LN(emb[idx[r]] + upd[b, idx[r], :]) * sc + bi
// grid: (nrows, B), block: 256
__global__ __launch_bounds__(256)
void gather_ln_kernel(const float* __restrict__ emb, const float* __restrict__ upd,
                      const int* __restrict__ idx,
                      const float* __restrict__ sc, const float* __restrict__ bi,
                      float* __restrict__ out) {
    __shared__ float red[16];
    int r = blockIdx.x, b = blockIdx.y, t = threadIdx.x;
    int nrows = gridDim.x;
    int j = idx[r];
    float x = emb[(size_t)j * Dm + t] + upd[((size_t)b * NS + j) * Dm + t];
    float2 mv = block_meanrstd(x, red);
    out[((size_t)b * nrows + r) * Dm + t] = (x - mv.x) * mv.y * sc[t] + bi[t];
}

// out[row, :] = LN(in[row, :]) * sc + bi     grid: (M), block: 256
__global__ __launch_bounds__(256)
void row_ln_kernel(const float* __restrict__ in,
                   const float* __restrict__ sc, const float* __restrict__ bi,
                   float* __restrict__ out) {
    __shared__ float red[16];
    size_t row = (size_t)blockIdx.x * Dm;
    int t = threadIdx.x;
    float x = in[row + t];
    float2 mv = block_meanrstd(x, red);
    out[row + t] = (x - mv.x) * mv.y * sc[t] + bi[t];
}

// C[M,256] = A[M,256] @ W[256,256] (+bias)(+gelu)
// BM=64, BN=64, BK=16, 256 threads, 4x4 per thread. grid: (4, M/64)
template <int EPI>
__global__ __launch_bounds__(256)
void gemm_kernel(const float* __restrict__ A, const float* __restrict__ W,
                 const float* __restrict__ bias, float* __restrict__ C) {
    __shared__ float As[16][65];   // transposed A tile, padded
    __shared__ float Bs[16][64];
    int bx = blockIdx.x, by = blockIdx.y;
    int tid = threadIdx.x;
    int tx = tid & 15, ty = tid >> 4;
    float acc[4][4] = {};
    int ar = tid >> 2, ac = (tid & 3) * 4;       // A tile load coords
    int br = tid >> 4, bc = (tid & 15) * 4;      // B tile load coords
    const float* Ag = A + ((size_t)by * 64 + ar) * 256;
    for (int k0 = 0; k0 < 256; k0 += 16) {
        float4 av = *(const float4*)&Ag[k0 + ac];
        As[ac + 0][ar] = av.x; As[ac + 1][ar] = av.y;
        As[ac + 2][ar] = av.z; As[ac + 3][ar] = av.w;
        float4 bv = *(const float4*)&W[(size_t)(k0 + br) * 256 + bx * 64 + bc];
        *(float4*)&Bs[br][bc] = bv;
        __syncthreads();
        #pragma unroll
        for (int kk = 0; kk < 16; kk++) {
            float a[4], bb[4];
            #pragma unroll
            for (int i = 0; i < 4; i++) a[i] = As[kk][ty * 4 + i];
            float4 b4 = *(const float4*)&Bs[kk][tx * 4];
            bb[0] = b4.x; bb[1] = b4.y; bb[2] = b4.z; bb[3] = b4.w;
            #pragma unroll
            for (int i = 0; i < 4; i++)
                #pragma unroll
                for (int jj = 0; jj < 4; jj++)
                    acc[i][jj] += a[i] * bb[jj];
        }
        __syncthreads();
    }
    #pragma unroll
    for (int i = 0; i < 4; i++) {
        size_t row = (size_t)by * 64 + ty * 4 + i;
        int col = bx * 64 + tx * 4;
        float4 v;
        float* vp = &v.x;
        #pragma unroll
        for (int jj = 0; jj < 4; jj++) {
            float u = acc[i][jj];
            if (EPI >= 1) u += bias[col + jj];
            if (EPI == 2) u = gelu_tanh(u);
            vp[jj] = u;
        }
        *(float4*)&C[row * 256 + col] = v;
    }
}

// Fused masked attention (flash-style, fp32).
// grid: (NQ/64, H, B), 256 threads (8 warps x 8 query rows each).
// Lane handles keys {lane, lane+32} of each 64-key tile; dims {lane, lane+32} of acc.
__global__ __launch_bounds__(256)
void attn_kernel(const float* __restrict__ Qg_, const float* __restrict__ Kg_,
                 const float* __restrict__ Vg_, const float* __restrict__ mask,
                 float* __restrict__ ctx) {
    const int TQ = 64, TK = 64;
    __shared__ float Qs[TQ][DH + 2];
    __shared__ float Ks[TK][DH + 2];
    __shared__ float Vs[TK][DH + 2];
    int qt = blockIdx.x, h = blockIdx.y, b = blockIdx.z;
    int tid = threadIdx.x, warp = tid >> 5, lane = tid & 31;

    const float* Qg = Qg_ + ((size_t)b * NQ + qt * TQ) * Dm + h * DH;
    for (int i = tid; i < TQ * 16; i += 256) {
        int r = i >> 4, c = (i & 15) * 4;
        float4 v = *(const float4*)&Qg[(size_t)r * Dm + c];
        Qs[r][c] = v.x; Qs[r][c + 1] = v.y; Qs[r][c + 2] = v.z; Qs[r][c + 3] = v.w;
    }

    float mrow[8], lrow[8], acc[8][2];
    #pragma unroll
    for (int r = 0; r < 8; r++) {
        mrow[r] = -1e30f; lrow[r] = 0.f; acc[r][0] = 0.f; acc[r][1] = 0.f;
    }
    __syncthreads();

    int qbase = qt * TQ + warp * 8;
    for (int k0 = 0; k0 < NK; k0 += TK) {
        const float* Kg = Kg_ + ((size_t)b * NK + k0) * Dm + h * DH;
        const float* Vg = Vg_ + ((size_t)b * NK + k0) * Dm + h * DH;
        for (int i = tid; i < TK * 16; i += 256) {
            int r = i >> 4, c = (i & 15) * 4;
            float4 kv = *(const float4*)&Kg[(size_t)r * Dm + c];
            Ks[r][c] = kv.x; Ks[r][c + 1] = kv.y; Ks[r][c + 2] = kv.z; Ks[r][c + 3] = kv.w;
            float4 vv = *(const float4*)&Vg[(size_t)r * Dm + c];
            Vs[r][c] = vv.x; Vs[r][c + 1] = vv.y; Vs[r][c + 2] = vv.z; Vs[r][c + 3] = vv.w;
        }
        __syncthreads();

        float s[8][2];
        #pragma unroll
        for (int r = 0; r < 8; r++) { s[r][0] = 0.f; s[r][1] = 0.f; }
        #pragma unroll
        for (int d = 0; d < DH; d += 2) {
            float2 ka = *(const float2*)&Ks[lane][d];
            float2 kb = *(const float2*)&Ks[lane + 32][d];
            #pragma unroll
            for (int r = 0; r < 8; r++) {
                float2 qv = *(const float2*)&Qs[warp * 8 + r][d];
                s[r][0] += qv.x * ka.x + qv.y * ka.y;
                s[r][1] += qv.x * kb.x + qv.y * kb.y;
            }
        }
        // mask + scale
        #pragma unroll
        for (int r = 0; r < 8; r++) {
            float m0 = mask[(size_t)(qbase + r) * NK + k0 + lane];
            float m1 = mask[(size_t)(qbase + r) * NK + k0 + lane + 32];
            s[r][0] = (m0 > 0.5f) ? s[r][0] * ATT_SCALE : -1e9f;
            s[r][1] = (m1 > 0.5f) ? s[r][1] * ATT_SCALE : -1e9f;
        }
        // online softmax update
        #pragma unroll
        for (int r = 0; r < 8; r++) {
            float mx = fmaxf(s[r][0], s[r][1]);
            #pragma unroll
            for (int o = 16; o > 0; o >>= 1)
                mx = fmaxf(mx, __shfl_xor_sync(0xffffffffu, mx, o));
            float mnew = fmaxf(mrow[r], mx);
            float alpha = __expf(mrow[r] - mnew);
            float p0 = __expf(s[r][0] - mnew);
            float p1 = __expf(s[r][1] - mnew);
            float ps = p0 + p1;
            #pragma unroll
            for (int o = 16; o > 0; o >>= 1)
                ps += __shfl_xor_sync(0xffffffffu, ps, o);
            lrow[r] = lrow[r] * alpha + ps;
            mrow[r] = mnew;
            acc[r][0] *= alpha; acc[r][1] *= alpha;
            s[r][0] = p0; s[r][1] = p1;
        }
        // ctx accumulate
        #pragma unroll 8
        for (int kk = 0; kk < 32; kk++) {
            float v0 = Vs[kk][lane];
            float v1 = Vs[kk][lane + 32];
            float v2 = Vs[kk + 32][lane];
            float v3 = Vs[kk + 32][lane + 32];
            #pragma unroll
            for (int r = 0; r < 8; r++) {
                float p0 = __shfl_sync(0xffffffffu, s[r][0], kk);
                float p1 = __shfl_sync(0xffffffffu, s[r][1], kk);
                acc[r][0] += p0 * v0 + p1 * v2;
                acc[r][1] += p0 * v1 + p1 * v3;
            }
        }
        __syncthreads();
    }
    #pragma unroll
    for (int r = 0; r < 8; r++) {
        float invl = 1.0f / lrow[r];
        size_t row = ((size_t)b * NQ + qbase + r) * Dm + h * DH;
        ctx[row + lane] = acc[r][0] * invl;
        ctx[row + lane + 32] = acc[r][1] * invl;
    }
}

// res = LN_eff( LN_outer(h + ffn) ); scatter-add into upd and out.
// grid: (NQ, B), block 256
__global__ __launch_bounds__(256)
void final_scatter_kernel(const float* __restrict__ hbuf, const float* __restrict__ fbuf,
                          const int* __restrict__ idx,
                          const float* __restrict__ os, const float* __restrict__ ob,
                          const float* __restrict__ es, const float* __restrict__ eb,
                          float* __restrict__ upd, float* __restrict__ out) {
    __shared__ float red[16];
    int r = blockIdx.x, b = blockIdx.y, t = threadIdx.x;
    size_t row = ((size_t)b * NQ + r) * Dm;
    float x = hbuf[row + t] + fbuf[row + t];
    float2 mv = block_meanrstd(x, red);
    float y = (x - mv.x) * mv.y * os[t] + ob[t];
    float2 mv2 = block_meanrstd(y, red);
    float res = (y - mv2.x) * mv2.y * es[t] + eb[t];
    int j = idx[r];
    size_t o = ((size_t)b * NS + j) * Dm + t;
    atomicAdd(&upd[o], res);
    atomicAdd(&out[o], res);
}

// ---------------- host launcher ----------------
extern "C" void kernel_launch(void* const* d_in, const int* in_sizes, int n_in,
                              void* d_out, int out_size) {
    const float* update = (const float*)d_in[0];
    const float* emb    = (const float*)d_in[1];
    const float* mask   = (const float*)d_in[2];
    const float* Wq     = (const float*)d_in[3];
    const float* Wk     = (const float*)d_in[4];
    const float* Wv     = (const float*)d_in[5];
    const float* Wo     = (const float*)d_in[6];
    const float* W1     = (const float*)d_in[7];
    const float* b1     = (const float*)d_in[8];
    const float* W2     = (const float*)d_in[9];
    const float* b2     = (const float*)d_in[10];
    const float* sys_s  = (const float*)d_in[11];
    const float* sys_b  = (const float*)d_in[12];
    const float* eff_s  = (const float*)d_in[13];
    const float* eff_b  = (const float*)d_in[14];
    const float* in_s   = (const float*)d_in[15];
    const float* in_b   = (const float*)d_in[16];
    const float* out_s  = (const float*)d_in[17];
    const float* out_b  = (const float*)d_in[18];
    const int*   qidx   = (const int*)d_in[19];
    const int*   kidx   = (const int*)d_in[20];
    float* out = (float*)d_out;

    float *p_upd, *p_qn, *p_kn, *p_Q, *p_K, *p_V, *p_ctx, *p_h, *p_t, *p_r;
    cudaGetSymbolAddress((void**)&p_upd, g_upd);
    cudaGetSymbolAddress((void**)&p_qn,  g_qn);
    cudaGetSymbolAddress((void**)&p_kn,  g_kn);
    cudaGetSymbolAddress((void**)&p_Q,   g_Q);
    cudaGetSymbolAddress((void**)&p_K,   g_K);
    cudaGetSymbolAddress((void**)&p_V,   g_V);
    cudaGetSymbolAddress((void**)&p_ctx, g_ctx);
    cudaGetSymbolAddress((void**)&p_h,   g_h);
    cudaGetSymbolAddress((void**)&p_t,   g_t);
    cudaGetSymbolAddress((void**)&p_r,   g_r);

    cudaMemsetAsync(d_out, 0, (size_t)out_size * sizeof(float), 0);
    cudaMemcpyAsync(p_upd, update, (size_t)Bz * NS * Dm * sizeof(float),
                    cudaMemcpyDeviceToDevice, 0);

    for (int l = 0; l < Ll; l++) {
        const int* qi = qidx + l * NQ;
        const int* ki = kidx + l * NK;
        const float* mk = mask + (size_t)l * NQ * NK;

        gather_ln_kernel<<<dim3(NQ, Bz), 256>>>(emb, p_upd, qi, sys_s, sys_b, p_qn);
        gather_ln_kernel<<<dim3(NK, Bz), 256>>>(emb, p_upd, ki, sys_s, sys_b, p_kn);

        gemm_kernel<0><<<dim3(4, (Bz * NQ) / 64), 256>>>(p_qn, Wq, nullptr, p_Q);
        gemm_kernel<0><<<dim3(4, (Bz * NK) / 64), 256>>>(p_kn, Wk, nullptr, p_K);
        gemm_kernel<0><<<dim3(4, (Bz * NK) / 64), 256>>>(p_kn, Wv, nullptr, p_V);

        attn_kernel<<<dim3(NQ / 64, Hh, Bz), 256>>>(p_Q, p_K, p_V, mk, p_ctx);

        gemm_kernel<0><<<dim3(4, (Bz * NQ) / 64), 256>>>(p_ctx, Wo, nullptr, p_t);
        row_ln_kernel<<<Bz * NQ, 256>>>(p_t, in_s, in_b, p_h);

        gemm_kernel<2><<<dim3(4, (Bz * NQ) / 64), 256>>>(p_h, W1, b1, p_t);
        gemm_kernel<1><<<dim3(4, (Bz * NQ) / 64), 256>>>(p_t, W2, b2, p_r);

        final_scatter_kernel<<<dim3(NQ, Bz), 256>>>(p_h, p_r, qi,
                                                    out_s, out_b, eff_s, eff_b,
                                                    p_upd, out);
    }
}